// round 12
// baseline (speedup 1.0000x reference)
#include <cuda_runtime.h>
#include <cstdint>

#define C_INN 128
#define C_OUTT 64
#define BB 8
#define NN 2048
#define LOG2E 1.4426950408889634f

// ---------------------------------------------------------------------------
// Scratch (__device__ globals: allocation-free per harness rules)
// ---------------------------------------------------------------------------
__device__ float  g_Wh[BB * NN * C_OUTT];       // tf32-rounded Wh, 4 MB
__device__ float2 g_E1i[BB * NN];               // {exp(f1), exp(0.2 f1)}
__device__ float2 g_E2i[BB * NN];               // {exp(f2), exp(0.2 f2)}
__device__ unsigned g_Mt[(NN / 32) * NN];       // transposed bitmask [word][i]
__device__ float  g_Wt[C_INN * C_OUTT];         // tf32-pre-rounded W
__device__ float2 g_w12[C_INN];                 // {W@a1, W@a2} per channel

__device__ __forceinline__ float fast_exp(float x) {
    float r;
    asm("ex2.approx.f32 %0, %1;" : "=f"(r) : "f"(x * LOG2E));
    return r;
}
__device__ __forceinline__ uint32_t cvt_tf32(float f) {
    uint32_t u;
    asm("cvt.rna.tf32.f32 %0, %1;" : "=r"(u) : "f"(f));
    return u;
}
__device__ __forceinline__ float tf32f(float f) {
    return __uint_as_float(cvt_tf32(f));
}
__device__ __forceinline__ uint32_t smem_u32(const void* p) {
    return (uint32_t)__cvta_generic_to_shared(p);
}
__device__ __forceinline__ void cpa16(uint32_t d, const void* s) {
    asm volatile("cp.async.cg.shared.global [%0], [%1], 16;" :: "r"(d), "l"(s));
}
__device__ __forceinline__ void cpa8(uint32_t d, const void* s) {
    asm volatile("cp.async.ca.shared.global [%0], [%1], 8;" :: "r"(d), "l"(s));
}
__device__ __forceinline__ void cpa_commit_wait0() {
    asm volatile("cp.async.commit_group;\n\tcp.async.wait_group 0;" ::: "memory");
}

// ---------------------------------------------------------------------------
// Kernel 1: bit-pack mask via warp ballot, SMEM-tiled TRANSPOSED writes.
// Block = 16 i-rows x 64 words (full A rows); grid 128 x 256 thr.
// Reads: 32 consecutive ints/lane -> ballot -> 1 mask word (coalesced 128B).
// Writes: uint4 chunks, 64B contiguous per g_Mt line (full sectors).
// Block 0 additionally does the one-time W prep.
// ---------------------------------------------------------------------------
__global__ void __launch_bounds__(256) k_mask(const int* __restrict__ A,
                                              const float* __restrict__ W,
                                              const float* __restrict__ attn)
{
    __shared__ unsigned tile[64 * 16];      // [ww][i], 4KB
    int t = threadIdx.x, lane = t & 31, wp = t >> 5;
    int i0 = blockIdx.x * 16;

    // each warp owns i in {2*wp, 2*wp+1}, all 64 words; 8-deep load batches
    #pragma unroll
    for (int it = 0; it < 128; it += 8) {
        int vals[8];
        #pragma unroll
        for (int u = 0; u < 8; u++) {
            int p = it + u;
            int i = wp * 2 + (p >> 6), ww = p & 63;
            vals[u] = A[(size_t)(i0 + i) * NN + ww * 32 + lane];
        }
        #pragma unroll
        for (int u = 0; u < 8; u++) {
            int p = it + u;
            int i = wp * 2 + (p >> 6), ww = p & 63;
            unsigned word = __ballot_sync(0xffffffffu, vals[u] > 0);
            if (lane == 0) tile[ww * 16 + i] = word;
        }
    }
    __syncthreads();

    // transposed write: thread -> (ww = t>>2, 4-word chunk q = t&3)
    {
        int ww = t >> 2, q = t & 3;
        uint4 v = *(const uint4*)&tile[ww * 16 + q * 4];
        *(uint4*)&g_Mt[(size_t)ww * NN + i0 + q * 4] = v;
    }

    if (blockIdx.x == 0) {
        #pragma unroll
        for (int k = 0; k < 32; k++) {
            int idx = t + k * 256;
            g_Wt[idx] = tf32f(W[idx]);
        }
        if (t < 128) {
            float w1 = 0.f, w2 = 0.f;
            const float* wrow = W + t * C_OUTT;
            #pragma unroll 8
            for (int nn2 = 0; nn2 < 64; nn2++) {
                float wv = wrow[nn2];
                w1 = fmaf(wv, attn[nn2], w1);
                w2 = fmaf(wv, attn[64 + nn2], w2);
            }
            g_w12[t] = make_float2(w1, w2);
        }
    }
}

// ---------------------------------------------------------------------------
// Kernel 2: Wh = x @ W via tf32 mma.sync, cp.async-staged, prep-assisted.
// (R11 config — rel_err-proven 4.0e-4.)
// ---------------------------------------------------------------------------
__global__ void __launch_bounds__(256) k_wh(const float* __restrict__ x)
{
    extern __shared__ float sm[];
    float*  xs  = sm;                       // 64 x 132
    float*  Ws  = sm + 64 * 132;            // 128 x 72
    float2* w12 = (float2*)(Ws + 128 * 72); // 128 x {w1,w2}

    int t = threadIdx.x, wid = t >> 5, lane = t & 31;
    int g = lane >> 2, tk = lane & 3;
    int warpM = wid >> 1, warpN = wid & 1;
    int base = blockIdx.x * 64;

    uint32_t xs_a  = smem_u32(xs);
    uint32_t ws_a  = smem_u32(Ws);
    uint32_t w12_a = smem_u32(w12);

    {
        const float4* xr = (const float4*)(x + (size_t)base * C_INN);
        #pragma unroll
        for (int k = 0; k < 8; k++) {
            int i4 = t + k * 256;
            int row = i4 >> 5, c = (i4 & 31) << 2;
            cpa16(xs_a + (uint32_t)(row * 132 + c) * 4u, xr + i4);
        }
        const float4* wr = (const float4*)g_Wt;
        #pragma unroll
        for (int k = 0; k < 8; k++) {
            int i4 = t + k * 256;
            int c = i4 >> 4, nn2 = (i4 & 15) << 2;
            cpa16(ws_a + (uint32_t)(c * 72 + nn2) * 4u, wr + i4);
        }
        if (t < 128) cpa8(w12_a + (uint32_t)t * 8u, g_w12 + t);
        cpa_commit_wait0();
    }
    __syncthreads();

    int r0 = warpM * 16;
    float acc[4][4];
    #pragma unroll
    for (int nt = 0; nt < 4; nt++)
        #pragma unroll
        for (int k = 0; k < 4; k++) acc[nt][k] = 0.f;

    #pragma unroll
    for (int ks = 0; ks < 16; ks++) {
        int c0 = ks * 8;
        uint32_t a0 = cvt_tf32(xs[(r0 + g) * 132 + c0 + tk]);
        uint32_t a1 = cvt_tf32(xs[(r0 + g + 8) * 132 + c0 + tk]);
        uint32_t a2 = cvt_tf32(xs[(r0 + g) * 132 + c0 + tk + 4]);
        uint32_t a3 = cvt_tf32(xs[(r0 + g + 8) * 132 + c0 + tk + 4]);
        const float* brow = Ws + (c0 + tk) * 72 + warpN * 32 + g;
        #pragma unroll
        for (int nt = 0; nt < 4; nt++) {
            uint32_t ub0 = __float_as_uint(brow[nt * 8]);
            uint32_t ub1 = __float_as_uint(brow[288 + nt * 8]);
            asm volatile(
                "mma.sync.aligned.m16n8k8.row.col.f32.tf32.tf32.f32 "
                "{%0,%1,%2,%3}, {%4,%5,%6,%7}, {%8,%9}, {%0,%1,%2,%3};"
                : "+f"(acc[nt][0]), "+f"(acc[nt][1]), "+f"(acc[nt][2]), "+f"(acc[nt][3])
                : "r"(a0), "r"(a1), "r"(a2), "r"(a3), "r"(ub0), "r"(ub1));
        }
    }

    {
        int row = t >> 2, q = t & 3;
        const float4* xv4 = (const float4*)&xs[row * 132 + q * 32];
        const float4* wv4 = (const float4*)(w12 + q * 32);
        float f1 = 0.f, f2 = 0.f;
        #pragma unroll
        for (int k = 0; k < 8; k++) {
            float4 xv = xv4[k];
            float4 wa = wv4[2 * k], wb = wv4[2 * k + 1];
            f1 += xv.x * wa.x + xv.y * wa.z + xv.z * wb.x + xv.w * wb.z;
            f2 += xv.x * wa.y + xv.y * wa.w + xv.z * wb.y + xv.w * wb.w;
        }
        f1 += __shfl_xor_sync(0xffffffffu, f1, 1);
        f1 += __shfl_xor_sync(0xffffffffu, f1, 2);
        f2 += __shfl_xor_sync(0xffffffffu, f2, 1);
        f2 += __shfl_xor_sync(0xffffffffu, f2, 2);
        if (q == 0) {
            int gr = base + row;
            g_E1i[gr] = make_float2(fast_exp(f1), fast_exp(0.2f * f1));
            g_E2i[gr] = make_float2(fast_exp(f2), fast_exp(0.2f * f2));
        }
    }

    #pragma unroll
    for (int nt = 0; nt < 4; nt++) {
        int nn2 = warpN * 32 + nt * 8 + tk * 2;
        *(float2*)&g_Wh[(size_t)(base + r0 + g) * C_OUTT + nn2] =
            make_float2(tf32f(acc[nt][0]), tf32f(acc[nt][1]));
        *(float2*)&g_Wh[(size_t)(base + r0 + g + 8) * C_OUTT + nn2] =
            make_float2(tf32f(acc[nt][2]), tf32f(acc[nt][3]));
    }
}

// ---------------------------------------------------------------------------
// Kernel 3: fused P-build + mma.sync tf32 aggregation, K-split warp pairs.
// (R5/R8 proven configuration — untouched.)
// ---------------------------------------------------------------------------
__global__ void __launch_bounds__(512, 1) k_gat(float* __restrict__ out)
{
    __shared__ float    Whs[128 * 72];
    __shared__ float2   E2s[128];
    __shared__ unsigned Msh[4][128];

    int t = threadIdx.x;
    int lane = t & 31, w = t >> 5;
    int warpM = w >> 1, kwarp = w & 1;
    int g = lane >> 2, tk = lane & 3;
    int b = blockIdx.x >> 4, i0 = (blockIdx.x & 15) << 7;
    int b2048 = b * NN;

    int r0 = warpM * 16 + g, r1 = r0 + 8;
    float2 e1a = g_E1i[b2048 + i0 + r0];
    float2 e1b = g_E1i[b2048 + i0 + r1];

    float c[8][4];
    #pragma unroll
    for (int nt = 0; nt < 8; nt++)
        #pragma unroll
        for (int k = 0; k < 4; k++) c[nt][k] = 0.f;
    float z0 = 0.f, z1 = 0.f;

    unsigned mt0 = 1u << tk;
    unsigned mt1 = 16u << tk;

    const float4* wh4 = (const float4*)(g_Wh + (size_t)b2048 * C_OUTT);

    float4 pw[4]; unsigned pm; float2 pe;
    {
        #pragma unroll
        for (int k = 0; k < 4; k++) pw[k] = wh4[t + k * 512];
        pm = g_Mt[(size_t)(t >> 7) * NN + i0 + (t & 127)];
        if (t < 128) pe = g_E2i[b2048 + t];
    }

    for (int jt = 0; jt < 16; jt++) {
        __syncthreads();
        #pragma unroll
        for (int k = 0; k < 4; k++) {
            int idx = t + k * 512;
            *(float4*)&Whs[(idx >> 4) * 72 + ((idx & 15) << 2)] = pw[k];
        }
        Msh[t >> 7][t & 127] = pm;
        if (t < 128) E2s[t] = pe;
        __syncthreads();

        {
            int jn = (jt + 1) & 15;
            #pragma unroll
            for (int k = 0; k < 4; k++) pw[k] = wh4[jn * 2048 + t + k * 512];
            pm = g_Mt[(size_t)(jn * 4 + (t >> 7)) * NN + i0 + (t & 127)];
            if (t < 128) pe = g_E2i[b2048 + jn * 128 + t];
        }

        unsigned mw0 = 0, mw1 = 0;
        #pragma unroll
        for (int ks = 0; ks < 8; ks++) {
            int ksg = kwarp * 8 + ks;
            if ((ks & 3) == 0) {
                mw0 = Msh[kwarp * 2 + (ks >> 2)][r0];
                mw1 = Msh[kwarp * 2 + (ks >> 2)][r1];
            }
            int j0 = ksg * 8;
            float2 ea = E2s[j0 + tk];
            float2 eb = E2s[j0 + tk + 4];
            unsigned s0 = mt0 << ((ks & 3) * 8);
            unsigned s1 = mt1 << ((ks & 3) * 8);

            float m;
            m = fmaxf(e1a.x * ea.x, e1a.y * ea.y);
            float a0 = (mw0 & s0) ? m : 0.f;
            m = fmaxf(e1b.x * ea.x, e1b.y * ea.y);
            float a1 = (mw1 & s0) ? m : 0.f;
            m = fmaxf(e1a.x * eb.x, e1a.y * eb.y);
            float a2 = (mw0 & s1) ? m : 0.f;
            m = fmaxf(e1b.x * eb.x, e1b.y * eb.y);
            float a3 = (mw1 & s1) ? m : 0.f;

            z0 += a0 + a2;
            z1 += a1 + a3;

            uint32_t ua0 = __float_as_uint(a0), ua1 = __float_as_uint(a1);
            uint32_t ua2 = __float_as_uint(a2), ua3 = __float_as_uint(a3);

            const float* brow = Whs + (j0 + tk) * 72 + g;
            #pragma unroll
            for (int nt = 0; nt < 8; nt++) {
                uint32_t ub0 = __float_as_uint(brow[nt * 8]);
                uint32_t ub1 = __float_as_uint(brow[288 + nt * 8]);
                asm volatile(
                    "mma.sync.aligned.m16n8k8.row.col.f32.tf32.tf32.f32 "
                    "{%0,%1,%2,%3}, {%4,%5,%6,%7}, {%8,%9}, {%0,%1,%2,%3};"
                    : "+f"(c[nt][0]), "+f"(c[nt][1]), "+f"(c[nt][2]), "+f"(c[nt][3])
                    : "r"(ua0), "r"(ua1), "r"(ua2), "r"(ua3), "r"(ub0), "r"(ub1));
            }
        }
    }

    z0 += __shfl_xor_sync(0xffffffffu, z0, 1);
    z0 += __shfl_xor_sync(0xffffffffu, z0, 2);
    z1 += __shfl_xor_sync(0xffffffffu, z1, 1);
    z1 += __shfl_xor_sync(0xffffffffu, z1, 2);

    __syncthreads();
    float4* red4 = (float4*)Whs;
    float2* zred = (float2*)((char*)Whs + 32768);

    if (kwarp == 1) {
        #pragma unroll
        for (int nt = 0; nt < 8; nt++)
            red4[(warpM * 8 + nt) * 32 + lane] =
                make_float4(c[nt][0], c[nt][1], c[nt][2], c[nt][3]);
        zred[warpM * 32 + lane] = make_float2(z0, z1);
    }
    __syncthreads();

    if (kwarp == 0) {
        float2 zz = zred[warpM * 32 + lane];
        float inv0 = 1.f / (z0 + zz.x);
        float inv1 = 1.f / (z1 + zz.y);

        float* o0 = out + (size_t)(b2048 + i0 + r0) * C_OUTT + tk * 2;
        float* o1 = out + (size_t)(b2048 + i0 + r1) * C_OUTT + tk * 2;
        #pragma unroll
        for (int nt = 0; nt < 8; nt++) {
            float4 v = red4[(warpM * 8 + nt) * 32 + lane];
            *(float2*)(o0 + nt * 8) =
                make_float2((c[nt][0] + v.x) * inv0, (c[nt][1] + v.y) * inv0);
            *(float2*)(o1 + nt * 8) =
                make_float2((c[nt][2] + v.z) * inv1, (c[nt][3] + v.w) * inv1);
        }
    }
}

// ---------------------------------------------------------------------------
extern "C" void kernel_launch(void* const* d_in, const int* in_sizes, int n_in,
                              void* d_out, int out_size)
{
    const float* x    = (const float*)d_in[0];   // (8,2048,128) f32
    const int*   A    = (const int*)d_in[1];     // (2048,2048) i32
    const float* W    = (const float*)d_in[2];   // (128,64) f32
    const float* attn = (const float*)d_in[3];   // (128,1) f32
    float* out = (float*)d_out;                  // (8,2048,64) f32

    const int wh_smem = (64 * 132 + 128 * 72 + 256) * 4;   // 71680 B
    cudaFuncSetAttribute(k_wh, cudaFuncAttributeMaxDynamicSharedMemorySize, wh_smem);

    k_mask<<<NN / 16, 256>>>(A, W, attn);
    k_wh  <<<BB * NN / 64, 256, wh_smem>>>(x);
    k_gat <<<BB * (NN / 128), 512>>>(out);
}

// round 13
// speedup vs baseline: 1.0305x; 1.0305x over previous
#include <cuda_runtime.h>
#include <cstdint>

#define C_INN 128
#define C_OUTT 64
#define BB 8
#define NN 2048
#define LOG2E 1.4426950408889634f

// ---------------------------------------------------------------------------
// Scratch (__device__ globals: allocation-free per harness rules)
// ---------------------------------------------------------------------------
__device__ float  g_Wh[BB * NN * C_OUTT];       // tf32-rounded Wh, 4 MB
__device__ float2 g_E1i[BB * NN];               // {exp(f1), exp(0.2 f1)}
__device__ float2 g_E2i[BB * NN];               // {exp(f2), exp(0.2 f2)}
__device__ unsigned g_Mt[(NN / 32) * NN];       // transposed bitmask [word][i]
__device__ float  g_Wt[C_INN * C_OUTT];         // tf32-pre-rounded W
__device__ float2 g_w12[C_INN];                 // {W@a1, W@a2} per channel

__device__ __forceinline__ float fast_exp(float x) {
    float r;
    asm("ex2.approx.f32 %0, %1;" : "=f"(r) : "f"(x * LOG2E));
    return r;
}
__device__ __forceinline__ uint32_t cvt_tf32(float f) {
    uint32_t u;
    asm("cvt.rna.tf32.f32 %0, %1;" : "=r"(u) : "f"(f));
    return u;
}
__device__ __forceinline__ float tf32f(float f) {
    return __uint_as_float(cvt_tf32(f));
}
// pack two fp32 -> half2 {hi, lo}
__device__ __forceinline__ uint32_t packh2(float hi, float lo) {
    uint32_t r;
    asm("cvt.rn.satfinite.f16x2.f32 %0, %1, %2;" : "=r"(r) : "f"(hi), "f"(lo));
    return r;
}
__device__ __forceinline__ uint32_t smem_u32(const void* p) {
    return (uint32_t)__cvta_generic_to_shared(p);
}
__device__ __forceinline__ void cpa16(uint32_t d, const void* s) {
    asm volatile("cp.async.cg.shared.global [%0], [%1], 16;" :: "r"(d), "l"(s));
}
__device__ __forceinline__ void cpa8(uint32_t d, const void* s) {
    asm volatile("cp.async.ca.shared.global [%0], [%1], 8;" :: "r"(d), "l"(s));
}
__device__ __forceinline__ void cpa_commit_wait0() {
    asm volatile("cp.async.commit_group;\n\tcp.async.wait_group 0;" ::: "memory");
}

// ---------------------------------------------------------------------------
// Kernel 1: bit-pack mask via warp ballot; 16i x 16w tiles; grid 512.
// Reads 128B-coalesced; writes uint4 (64B/line contiguous). Blk 0: W prep.
// ---------------------------------------------------------------------------
__global__ void __launch_bounds__(256) k_mask(const int* __restrict__ A,
                                              const float* __restrict__ W,
                                              const float* __restrict__ attn)
{
    __shared__ unsigned tile[16 * 16];
    int t = threadIdx.x, lane = t & 31, wp = t >> 5;
    int ib = blockIdx.x >> 2, wb = blockIdx.x & 3;   // 128 i-tiles x 4 col-groups
    int i0 = ib * 16;

    // warp wp owns i in {2wp, 2wp+1}, 16 words each; batches of 8 loads
    #pragma unroll
    for (int it = 0; it < 32; it += 8) {
        int vals[8];
        #pragma unroll
        for (int u = 0; u < 8; u++) {
            int p = it + u;
            int i = wp * 2 + (p >> 4), ww = p & 15;
            vals[u] = A[(size_t)(i0 + i) * NN + wb * 512 + ww * 32 + lane];
        }
        #pragma unroll
        for (int u = 0; u < 8; u++) {
            int p = it + u;
            int i = wp * 2 + (p >> 4), ww = p & 15;
            unsigned word = __ballot_sync(0xffffffffu, vals[u] > 0);
            if (lane == 0) tile[ww * 16 + i] = word;
        }
    }
    __syncthreads();

    if (t < 64) {
        int ww = t >> 2, q = t & 3;
        uint4 v = *(const uint4*)&tile[ww * 16 + q * 4];
        *(uint4*)&g_Mt[(size_t)(wb * 16 + ww) * NN + i0 + q * 4] = v;
    }

    if (blockIdx.x == 0) {
        #pragma unroll
        for (int k = 0; k < 32; k++) {
            int idx = t + k * 256;
            g_Wt[idx] = tf32f(W[idx]);
        }
        if (t < 128) {
            float w1 = 0.f, w2 = 0.f;
            const float* wrow = W + t * C_OUTT;
            #pragma unroll 8
            for (int nn2 = 0; nn2 < 64; nn2++) {
                float wv = wrow[nn2];
                w1 = fmaf(wv, attn[nn2], w1);
                w2 = fmaf(wv, attn[64 + nn2], w2);
            }
            g_w12[t] = make_float2(w1, w2);
        }
    }
}

// ---------------------------------------------------------------------------
// Kernel 2: Wh = x @ W via tf32 mma.sync (R11 config, rel_err-proven).
// ---------------------------------------------------------------------------
__global__ void __launch_bounds__(256) k_wh(const float* __restrict__ x)
{
    extern __shared__ float sm[];
    float*  xs  = sm;                       // 64 x 132
    float*  Ws  = sm + 64 * 132;            // 128 x 72
    float2* w12 = (float2*)(Ws + 128 * 72); // 128 x {w1,w2}

    int t = threadIdx.x, wid = t >> 5, lane = t & 31;
    int g = lane >> 2, tk = lane & 3;
    int warpM = wid >> 1, warpN = wid & 1;
    int base = blockIdx.x * 64;

    uint32_t xs_a  = smem_u32(xs);
    uint32_t ws_a  = smem_u32(Ws);
    uint32_t w12_a = smem_u32(w12);

    {
        const float4* xr = (const float4*)(x + (size_t)base * C_INN);
        #pragma unroll
        for (int k = 0; k < 8; k++) {
            int i4 = t + k * 256;
            int row = i4 >> 5, c = (i4 & 31) << 2;
            cpa16(xs_a + (uint32_t)(row * 132 + c) * 4u, xr + i4);
        }
        const float4* wr = (const float4*)g_Wt;
        #pragma unroll
        for (int k = 0; k < 8; k++) {
            int i4 = t + k * 256;
            int c = i4 >> 4, nn2 = (i4 & 15) << 2;
            cpa16(ws_a + (uint32_t)(c * 72 + nn2) * 4u, wr + i4);
        }
        if (t < 128) cpa8(w12_a + (uint32_t)t * 8u, g_w12 + t);
        cpa_commit_wait0();
    }
    __syncthreads();

    int r0 = warpM * 16;
    float acc[4][4];
    #pragma unroll
    for (int nt = 0; nt < 4; nt++)
        #pragma unroll
        for (int k = 0; k < 4; k++) acc[nt][k] = 0.f;

    #pragma unroll
    for (int ks = 0; ks < 16; ks++) {
        int c0 = ks * 8;
        uint32_t a0 = cvt_tf32(xs[(r0 + g) * 132 + c0 + tk]);
        uint32_t a1 = cvt_tf32(xs[(r0 + g + 8) * 132 + c0 + tk]);
        uint32_t a2 = cvt_tf32(xs[(r0 + g) * 132 + c0 + tk + 4]);
        uint32_t a3 = cvt_tf32(xs[(r0 + g + 8) * 132 + c0 + tk + 4]);
        const float* brow = Ws + (c0 + tk) * 72 + warpN * 32 + g;
        #pragma unroll
        for (int nt = 0; nt < 4; nt++) {
            uint32_t ub0 = __float_as_uint(brow[nt * 8]);
            uint32_t ub1 = __float_as_uint(brow[288 + nt * 8]);
            asm volatile(
                "mma.sync.aligned.m16n8k8.row.col.f32.tf32.tf32.f32 "
                "{%0,%1,%2,%3}, {%4,%5,%6,%7}, {%8,%9}, {%0,%1,%2,%3};"
                : "+f"(acc[nt][0]), "+f"(acc[nt][1]), "+f"(acc[nt][2]), "+f"(acc[nt][3])
                : "r"(a0), "r"(a1), "r"(a2), "r"(a3), "r"(ub0), "r"(ub1));
        }
    }

    {
        int row = t >> 2, q = t & 3;
        const float4* xv4 = (const float4*)&xs[row * 132 + q * 32];
        const float4* wv4 = (const float4*)(w12 + q * 32);
        float f1 = 0.f, f2 = 0.f;
        #pragma unroll
        for (int k = 0; k < 8; k++) {
            float4 xv = xv4[k];
            float4 wa = wv4[2 * k], wb = wv4[2 * k + 1];
            f1 += xv.x * wa.x + xv.y * wa.z + xv.z * wb.x + xv.w * wb.z;
            f2 += xv.x * wa.y + xv.y * wa.w + xv.z * wb.y + xv.w * wb.w;
        }
        f1 += __shfl_xor_sync(0xffffffffu, f1, 1);
        f1 += __shfl_xor_sync(0xffffffffu, f1, 2);
        f2 += __shfl_xor_sync(0xffffffffu, f2, 1);
        f2 += __shfl_xor_sync(0xffffffffu, f2, 2);
        if (q == 0) {
            int gr = base + row;
            g_E1i[gr] = make_float2(fast_exp(f1), fast_exp(0.2f * f1));
            g_E2i[gr] = make_float2(fast_exp(f2), fast_exp(0.2f * f2));
        }
    }

    #pragma unroll
    for (int nt = 0; nt < 4; nt++) {
        int nn2 = warpN * 32 + nt * 8 + tk * 2;
        *(float2*)&g_Wh[(size_t)(base + r0 + g) * C_OUTT + nn2] =
            make_float2(tf32f(acc[nt][0]), tf32f(acc[nt][1]));
        *(float2*)&g_Wh[(size_t)(base + r0 + g + 8) * C_OUTT + nn2] =
            make_float2(tf32f(acc[nt][2]), tf32f(acc[nt][3]));
    }
}

// ---------------------------------------------------------------------------
// Kernel 3: fused P-build + fp16 m16n8k16 mma aggregation, K-split warp pairs.
// Same structure as the proven R5 kernel; MMA count halved (4096 FLOP/instr).
// SMEM stays fp32 (stride 68: 2tk-step B loads conflict-free); fp16 operands
// packed in registers via cvt.rn.satfinite.f16x2 (same 10-bit mantissa as
// tf32 -> accuracy unchanged). Accumulate fp32.
// ---------------------------------------------------------------------------
__global__ void __launch_bounds__(512, 1) k_gat(float* __restrict__ out)
{
    __shared__ float    Whs[128 * 68];           // 34816 B; reused for reduction
    __shared__ alignas(16) float2 E2s[128];
    __shared__ unsigned Msh[4][128];

    int t = threadIdx.x;
    int lane = t & 31, w = t >> 5;
    int warpM = w >> 1, kwarp = w & 1;
    int g = lane >> 2, tk = lane & 3;
    int b = blockIdx.x >> 4, i0 = (blockIdx.x & 15) << 7;
    int b2048 = b * NN;

    int r0 = warpM * 16 + g, r1 = r0 + 8;
    float2 e1a = g_E1i[b2048 + i0 + r0];
    float2 e1b = g_E1i[b2048 + i0 + r1];

    float c[8][4];
    #pragma unroll
    for (int nt = 0; nt < 8; nt++)
        #pragma unroll
        for (int k = 0; k < 4; k++) c[nt][k] = 0.f;
    float z0 = 0.f, z1 = 0.f;

    const float4* wh4 = (const float4*)(g_Wh + (size_t)b2048 * C_OUTT);

    float4 pw[4]; unsigned pm; float2 pe;
    {
        #pragma unroll
        for (int k = 0; k < 4; k++) pw[k] = wh4[t + k * 512];
        pm = g_Mt[(size_t)(t >> 7) * NN + i0 + (t & 127)];
        if (t < 128) pe = g_E2i[b2048 + t];
    }

    for (int jt = 0; jt < 16; jt++) {
        __syncthreads();
        #pragma unroll
        for (int k = 0; k < 4; k++) {
            int idx = t + k * 512;
            *(float4*)&Whs[(idx >> 4) * 68 + ((idx & 15) << 2)] = pw[k];
        }
        Msh[t >> 7][t & 127] = pm;
        if (t < 128) E2s[t] = pe;
        __syncthreads();

        {
            int jn = (jt + 1) & 15;
            #pragma unroll
            for (int k = 0; k < 4; k++) pw[k] = wh4[jn * 2048 + t + k * 512];
            pm = g_Mt[(size_t)(jn * 4 + (t >> 7)) * NN + i0 + (t & 127)];
            if (t < 128) pe = g_E2i[b2048 + jn * 128 + t];
        }

        // this warp's 4 k16-steps (kwarp selects half of the 128-j tile)
        unsigned mw0 = 0, mw1 = 0;
        #pragma unroll
        for (int ksl = 0; ksl < 4; ksl++) {
            int s = kwarp * 4 + ksl;
            if ((ksl & 1) == 0) {
                mw0 = Msh[kwarp * 2 + (ksl >> 1)][r0];
                mw1 = Msh[kwarp * 2 + (ksl >> 1)][r1];
            }
            int j0 = s * 16;
            int bb = ((ksl & 1) << 4) + 2 * tk;
            float4 ea = *(const float4*)&E2s[j0 + 2 * tk];       // j, j+1
            float4 eb = *(const float4*)&E2s[j0 + 8 + 2 * tk];   // j+8, j+9

            float m;
            m = fmaxf(e1a.x * ea.x, e1a.y * ea.y); float w00 = ((mw0 >> bb) & 1u) ? m : 0.f;
            m = fmaxf(e1a.x * ea.z, e1a.y * ea.w); float w01 = ((mw0 >> (bb + 1)) & 1u) ? m : 0.f;
            m = fmaxf(e1a.x * eb.x, e1a.y * eb.y); float w02 = ((mw0 >> (bb + 8)) & 1u) ? m : 0.f;
            m = fmaxf(e1a.x * eb.z, e1a.y * eb.w); float w03 = ((mw0 >> (bb + 9)) & 1u) ? m : 0.f;
            m = fmaxf(e1b.x * ea.x, e1b.y * ea.y); float w10 = ((mw1 >> bb) & 1u) ? m : 0.f;
            m = fmaxf(e1b.x * ea.z, e1b.y * ea.w); float w11 = ((mw1 >> (bb + 1)) & 1u) ? m : 0.f;
            m = fmaxf(e1b.x * eb.x, e1b.y * eb.y); float w12_ = ((mw1 >> (bb + 8)) & 1u) ? m : 0.f;
            m = fmaxf(e1b.x * eb.z, e1b.y * eb.w); float w13 = ((mw1 >> (bb + 9)) & 1u) ? m : 0.f;

            z0 += (w00 + w01) + (w02 + w03);
            z1 += (w10 + w11) + (w12_ + w13);

            uint32_t a0 = packh2(w01, w00);
            uint32_t a1 = packh2(w11, w10);
            uint32_t a2 = packh2(w03, w02);
            uint32_t a3 = packh2(w13, w12_);

            const float* b0p = Whs + (j0 + 2 * tk) * 68 + g;
            const float* b1p = Whs + (j0 + 8 + 2 * tk) * 68 + g;
            #pragma unroll
            for (int nt = 0; nt < 8; nt++) {
                uint32_t ub0 = packh2(b0p[68 + nt * 8], b0p[nt * 8]);
                uint32_t ub1 = packh2(b1p[68 + nt * 8], b1p[nt * 8]);
                asm volatile(
                    "mma.sync.aligned.m16n8k16.row.col.f32.f16.f16.f32 "
                    "{%0,%1,%2,%3}, {%4,%5,%6,%7}, {%8,%9}, {%0,%1,%2,%3};"
                    : "+f"(c[nt][0]), "+f"(c[nt][1]), "+f"(c[nt][2]), "+f"(c[nt][3])
                    : "r"(a0), "r"(a1), "r"(a2), "r"(a3), "r"(ub0), "r"(ub1));
            }
        }
    }

    z0 += __shfl_xor_sync(0xffffffffu, z0, 1);
    z0 += __shfl_xor_sync(0xffffffffu, z0, 2);
    z1 += __shfl_xor_sync(0xffffffffu, z1, 1);
    z1 += __shfl_xor_sync(0xffffffffu, z1, 2);

    __syncthreads();
    float4* red4 = (float4*)Whs;                       // 32 KB
    float2* zred = (float2*)((char*)Whs + 32768);      // + 2 KB (fits 34816)

    if (kwarp == 1) {
        #pragma unroll
        for (int nt = 0; nt < 8; nt++)
            red4[(warpM * 8 + nt) * 32 + lane] =
                make_float4(c[nt][0], c[nt][1], c[nt][2], c[nt][3]);
        zred[warpM * 32 + lane] = make_float2(z0, z1);
    }
    __syncthreads();

    if (kwarp == 0) {
        float2 zz = zred[warpM * 32 + lane];
        float inv0 = 1.f / (z0 + zz.x);
        float inv1 = 1.f / (z1 + zz.y);

        float* o0 = out + (size_t)(b2048 + i0 + r0) * C_OUTT + tk * 2;
        float* o1 = out + (size_t)(b2048 + i0 + r1) * C_OUTT + tk * 2;
        #pragma unroll
        for (int nt = 0; nt < 8; nt++) {
            float4 v = red4[(warpM * 8 + nt) * 32 + lane];
            *(float2*)(o0 + nt * 8) =
                make_float2((c[nt][0] + v.x) * inv0, (c[nt][1] + v.y) * inv0);
            *(float2*)(o1 + nt * 8) =
                make_float2((c[nt][2] + v.z) * inv1, (c[nt][3] + v.w) * inv1);
        }
    }
}

// ---------------------------------------------------------------------------
extern "C" void kernel_launch(void* const* d_in, const int* in_sizes, int n_in,
                              void* d_out, int out_size)
{
    const float* x    = (const float*)d_in[0];   // (8,2048,128) f32
    const int*   A    = (const int*)d_in[1];     // (2048,2048) i32
    const float* W    = (const float*)d_in[2];   // (128,64) f32
    const float* attn = (const float*)d_in[3];   // (128,1) f32
    float* out = (float*)d_out;                  // (8,2048,64) f32

    const int wh_smem = (64 * 132 + 128 * 72 + 256) * 4;   // 71680 B
    cudaFuncSetAttribute(k_wh, cudaFuncAttributeMaxDynamicSharedMemorySize, wh_smem);

    k_mask<<<512, 256>>>(A, W, attn);
    k_wh  <<<BB * NN / 64, 256, wh_smem>>>(x);
    k_gat <<<BB * (NN / 128), 512>>>(out);
}

// round 16
// speedup vs baseline: 1.2727x; 1.2351x over previous
#include <cuda_runtime.h>
#include <cstdint>

#define C_INN 128
#define C_OUTT 64
#define BB 8
#define NN 2048
#define LOG2E 1.4426950408889634f

// ---------------------------------------------------------------------------
// Scratch (__device__ globals: allocation-free per harness rules)
// ---------------------------------------------------------------------------
__device__ unsigned g_Whh[BB * 64 * 1024];      // fp16 Wh, TRANSPOSED [b][n][j/2], 2MB
__device__ float2 g_E1i[BB * NN];               // {exp(f1), exp(0.2 f1)}
__device__ float2 g_E2i[BB * NN];               // {exp(f2), exp(0.2 f2)}
__device__ unsigned g_Mt[(NN / 32) * NN];       // transposed bitmask [word][i]

__device__ __forceinline__ float fast_exp(float x) {
    float r;
    asm("ex2.approx.f32 %0, %1;" : "=f"(r) : "f"(x * LOG2E));
    return r;
}
__device__ __forceinline__ uint32_t cvt_tf32(float f) {
    uint32_t u;
    asm("cvt.rna.tf32.f32 %0, %1;" : "=r"(u) : "f"(f));
    return u;
}
__device__ __forceinline__ float tf32f(float f) {
    return __uint_as_float(cvt_tf32(f));
}
// pack two fp32 -> half2 {lo, hi}
__device__ __forceinline__ uint32_t packh2(float hi, float lo) {
    uint32_t r;
    asm("cvt.rn.satfinite.f16x2.f32 %0, %1, %2;" : "=r"(r) : "f"(hi), "f"(lo));
    return r;
}
__device__ __forceinline__ uint32_t smem_u32(const void* p) {
    return (uint32_t)__cvta_generic_to_shared(p);
}
__device__ __forceinline__ void cpa16(uint32_t d, const void* s) {
    asm volatile("cp.async.cg.shared.global [%0], [%1], 16;" :: "r"(d), "l"(s));
}
__device__ __forceinline__ void cpa_commit_wait0() {
    asm volatile("cp.async.commit_group;\n\tcp.async.wait_group 0;" ::: "memory");
}

// ---------------------------------------------------------------------------
// Kernel 1: k_prep — fused Wh-GEMM (blocks 0..255) + mask pack (blocks 256..767).
// Disjoint inputs/outputs; overlaps wh's latency-bound path with mask's
// DRAM-bound streaming.
// ---------------------------------------------------------------------------
__global__ void __launch_bounds__(256) k_prep(const float* __restrict__ x,
                                              const int* __restrict__ A,
                                              const float* __restrict__ W,
                                              const float* __restrict__ attn)
{
    extern __shared__ float sm[];
    int t = threadIdx.x;

    if (blockIdx.x >= 256) {
        // ---------------- mask part (R13 logic, bid remapped) ----------------
        unsigned* tile = (unsigned*)sm;         // 16x16 words
        int bid = blockIdx.x - 256;
        int lane = t & 31, wp = t >> 5;
        int ib = bid >> 2, wb = bid & 3;
        int i0 = ib * 16;

        #pragma unroll
        for (int it = 0; it < 32; it += 8) {
            int vals[8];
            #pragma unroll
            for (int u = 0; u < 8; u++) {
                int p = it + u;
                int i = wp * 2 + (p >> 4), ww = p & 15;
                vals[u] = A[(size_t)(i0 + i) * NN + wb * 512 + ww * 32 + lane];
            }
            #pragma unroll
            for (int u = 0; u < 8; u++) {
                int p = it + u;
                int i = wp * 2 + (p >> 4), ww = p & 15;
                unsigned word = __ballot_sync(0xffffffffu, vals[u] > 0);
                if (lane == 0) tile[ww * 16 + i] = word;
            }
        }
        __syncthreads();
        if (t < 64) {
            int ww = t >> 2, q = t & 3;
            uint4 v = *(const uint4*)&tile[ww * 16 + q * 4];
            *(uint4*)&g_Mt[(size_t)(wb * 16 + ww) * NN + i0 + q * 4] = v;
        }
        return;
    }

    // ------------------------- wh part (R8/R11 hybrid) -----------------------
    float*  xs  = sm;                       // 64 x 132 (raw fp32 x)
    float*  Ws  = sm + 64 * 132;            // 128 x 72 (rna-rounded W)
    float2* w12 = (float2*)(Ws + 128 * 72); // 128 x {w1,w2}
    float*  WsT = sm;                       // epilogue transpose buf (reuses xs)

    int wid = t >> 5, lane = t & 31;
    int g = lane >> 2, tk = lane & 3;
    int warpM = wid >> 1, warpN = wid & 1;
    int base = blockIdx.x * 64;

    uint32_t xs_a = smem_u32(xs);
    {
        const float4* xr = (const float4*)(x + (size_t)base * C_INN);
        #pragma unroll
        for (int k = 0; k < 8; k++) {
            int i4 = t + k * 256;
            int row = i4 >> 5, c = (i4 & 31) << 2;
            cpa16(xs_a + (uint32_t)(row * 132 + c) * 4u, xr + i4);
        }
        cpa_commit_wait0();
    }
    // W: LDG + rna round + STS (proven R8 path)
    {
        const float4* wr = (const float4*)W;
        #pragma unroll
        for (int k = 0; k < 8; k++) {
            int i4 = t + k * 256;
            float4 v = wr[i4];
            int c = i4 >> 4, nn2 = (i4 & 15) << 2;
            *(float4*)&Ws[c * 72 + nn2] =
                make_float4(tf32f(v.x), tf32f(v.y), tf32f(v.z), tf32f(v.w));
        }
    }
    __syncthreads();

    if (t < 128) {
        float w1 = 0.f, w2 = 0.f;
        const float* wrow = Ws + t * 72;
        #pragma unroll 8
        for (int nn2 = 0; nn2 < 64; nn2++) {
            float wv = wrow[nn2];
            w1 = fmaf(wv, attn[nn2], w1);
            w2 = fmaf(wv, attn[64 + nn2], w2);
        }
        w12[t] = make_float2(w1, w2);
    }
    __syncthreads();

    int r0 = warpM * 16;
    float acc[4][4];
    #pragma unroll
    for (int nt = 0; nt < 4; nt++)
        #pragma unroll
        for (int k = 0; k < 4; k++) acc[nt][k] = 0.f;

    #pragma unroll
    for (int ks = 0; ks < 16; ks++) {
        int c0 = ks * 8;
        uint32_t a0 = cvt_tf32(xs[(r0 + g) * 132 + c0 + tk]);
        uint32_t a1 = cvt_tf32(xs[(r0 + g + 8) * 132 + c0 + tk]);
        uint32_t a2 = cvt_tf32(xs[(r0 + g) * 132 + c0 + tk + 4]);
        uint32_t a3 = cvt_tf32(xs[(r0 + g + 8) * 132 + c0 + tk + 4]);
        const float* brow = Ws + (c0 + tk) * 72 + warpN * 32 + g;
        #pragma unroll
        for (int nt = 0; nt < 4; nt++) {
            uint32_t ub0 = __float_as_uint(brow[nt * 8]);
            uint32_t ub1 = __float_as_uint(brow[288 + nt * 8]);
            asm volatile(
                "mma.sync.aligned.m16n8k8.row.col.f32.tf32.tf32.f32 "
                "{%0,%1,%2,%3}, {%4,%5,%6,%7}, {%8,%9}, {%0,%1,%2,%3};"
                : "+f"(acc[nt][0]), "+f"(acc[nt][1]), "+f"(acc[nt][2]), "+f"(acc[nt][3])
                : "r"(a0), "r"(a1), "r"(a2), "r"(a3), "r"(ub0), "r"(ub1));
        }
    }

    // f-pass (full fp32 x, w12)
    {
        int row = t >> 2, q = t & 3;
        const float4* xv4 = (const float4*)&xs[row * 132 + q * 32];
        const float4* wv4 = (const float4*)(w12 + q * 32);
        float f1 = 0.f, f2 = 0.f;
        #pragma unroll
        for (int k = 0; k < 8; k++) {
            float4 xv = xv4[k];
            float4 wa = wv4[2 * k], wb = wv4[2 * k + 1];
            f1 += xv.x * wa.x + xv.y * wa.z + xv.z * wb.x + xv.w * wb.z;
            f2 += xv.x * wa.y + xv.y * wa.w + xv.z * wb.y + xv.w * wb.w;
        }
        f1 += __shfl_xor_sync(0xffffffffu, f1, 1);
        f1 += __shfl_xor_sync(0xffffffffu, f1, 2);
        f2 += __shfl_xor_sync(0xffffffffu, f2, 1);
        f2 += __shfl_xor_sync(0xffffffffu, f2, 2);
        if (q == 0) {
            int gr = base + row;
            g_E1i[gr] = make_float2(fast_exp(f1), fast_exp(0.2f * f1));
            g_E2i[gr] = make_float2(fast_exp(f2), fast_exp(0.2f * f2));
        }
    }

    // epilogue: transpose via SMEM (xs reused), emit fp16 paired [n][j/2]
    __syncthreads();
    #pragma unroll
    for (int nt = 0; nt < 4; nt++) {
        int n = warpN * 32 + nt * 8 + tk * 2;
        WsT[(r0 + g) * 65 + n]     = acc[nt][0];
        WsT[(r0 + g) * 65 + n + 1] = acc[nt][1];
        WsT[(r0 + g + 8) * 65 + n]     = acc[nt][2];
        WsT[(r0 + g + 8) * 65 + n + 1] = acc[nt][3];
    }
    __syncthreads();
    {
        int b = base >> 11;
        int jw0 = (base & 2047) >> 1;
        unsigned* dst = g_Whh + (size_t)b * 65536;
        #pragma unroll
        for (int k = 0; k < 8; k++) {
            int wq = t + k * 256;
            int n = wq >> 5, jw = wq & 31;
            float lo = WsT[(2 * jw) * 65 + n];
            float hi = WsT[(2 * jw + 1) * 65 + n];
            dst[n * 1024 + jw0 + jw] = packh2(hi, lo);
        }
    }
}

// ---------------------------------------------------------------------------
// Kernel 2: fused P-build + fp16 m16n8k16 mma, K-split warp pairs.
// B operand pre-paired fp16 from g_Whh: per nt just 2 LDS.32, zero cvt.
// Shared buffer sized for the epilogue reduction (33792 B = 8448 u32),
// staging uses the first 4352 words (64 n x 68 u32 tile).
// ---------------------------------------------------------------------------
__global__ void __launch_bounds__(512, 1) k_gat(float* __restrict__ out)
{
    __shared__ alignas(16) unsigned WhT[8448];      // 33792 B (tile + reduction)
    __shared__ alignas(16) float2 E2s[128];
    __shared__ unsigned Msh[4][128];

    int t = threadIdx.x;
    int lane = t & 31, w = t >> 5;
    int warpM = w >> 1, kwarp = w & 1;
    int g = lane >> 2, tk = lane & 3;
    int b = blockIdx.x >> 4, i0 = (blockIdx.x & 15) << 7;
    int b2048 = b * NN;

    int r0 = warpM * 16 + g, r1 = r0 + 8;
    float2 e1a = g_E1i[b2048 + i0 + r0];
    float2 e1b = g_E1i[b2048 + i0 + r1];

    float c[8][4];
    #pragma unroll
    for (int nt = 0; nt < 8; nt++)
        #pragma unroll
        for (int k = 0; k < 4; k++) c[nt][k] = 0.f;
    float z0 = 0.f, z1 = 0.f;

    const uint4* whh4 = (const uint4*)(g_Whh + (size_t)b * 65536);

    // register prefetch buffers
    uint4 pwh[2]; unsigned pm; float2 pe;
    {
        #pragma unroll
        for (int k = 0; k < 2; k++) {
            int idx = t + k * 512;
            pwh[k] = whh4[(idx >> 4) * 256 + (idx & 15)];
        }
        pm = g_Mt[(size_t)(t >> 7) * NN + i0 + (t & 127)];
        if (t < 128) pe = g_E2i[b2048 + t];
    }

    for (int jt = 0; jt < 16; jt++) {
        __syncthreads();
        #pragma unroll
        for (int k = 0; k < 2; k++) {
            int idx = t + k * 512;
            *(uint4*)&WhT[(idx >> 4) * 68 + ((idx & 15) << 2)] = pwh[k];
        }
        Msh[t >> 7][t & 127] = pm;
        if (t < 128) E2s[t] = pe;
        __syncthreads();

        {
            int jn = (jt + 1) & 15;
            #pragma unroll
            for (int k = 0; k < 2; k++) {
                int idx = t + k * 512;
                pwh[k] = whh4[(idx >> 4) * 256 + jn * 16 + (idx & 15)];
            }
            pm = g_Mt[(size_t)(jn * 4 + (t >> 7)) * NN + i0 + (t & 127)];
            if (t < 128) pe = g_E2i[b2048 + jn * 128 + t];
        }

        unsigned mw0 = 0, mw1 = 0;
        #pragma unroll
        for (int ksl = 0; ksl < 4; ksl++) {
            int s = kwarp * 4 + ksl;
            if ((ksl & 1) == 0) {
                mw0 = Msh[kwarp * 2 + (ksl >> 1)][r0];
                mw1 = Msh[kwarp * 2 + (ksl >> 1)][r1];
            }
            int j0 = s * 16;
            int bb = ((ksl & 1) << 4) + 2 * tk;
            float4 ea = *(const float4*)&E2s[j0 + 2 * tk];       // j, j+1
            float4 eb = *(const float4*)&E2s[j0 + 8 + 2 * tk];   // j+8, j+9

            float m;
            m = fmaxf(e1a.x * ea.x, e1a.y * ea.y); float w00 = ((mw0 >> bb) & 1u) ? m : 0.f;
            m = fmaxf(e1a.x * ea.z, e1a.y * ea.w); float w01 = ((mw0 >> (bb + 1)) & 1u) ? m : 0.f;
            m = fmaxf(e1a.x * eb.x, e1a.y * eb.y); float w02 = ((mw0 >> (bb + 8)) & 1u) ? m : 0.f;
            m = fmaxf(e1a.x * eb.z, e1a.y * eb.w); float w03 = ((mw0 >> (bb + 9)) & 1u) ? m : 0.f;
            m = fmaxf(e1b.x * ea.x, e1b.y * ea.y); float w10 = ((mw1 >> bb) & 1u) ? m : 0.f;
            m = fmaxf(e1b.x * ea.z, e1b.y * ea.w); float w11 = ((mw1 >> (bb + 1)) & 1u) ? m : 0.f;
            m = fmaxf(e1b.x * eb.x, e1b.y * eb.y); float w12_ = ((mw1 >> (bb + 8)) & 1u) ? m : 0.f;
            m = fmaxf(e1b.x * eb.z, e1b.y * eb.w); float w13 = ((mw1 >> (bb + 9)) & 1u) ? m : 0.f;

            z0 += (w00 + w01) + (w02 + w03);
            z1 += (w10 + w11) + (w12_ + w13);

            uint32_t a0 = packh2(w01, w00);
            uint32_t a1 = packh2(w11, w10);
            uint32_t a2 = packh2(w03, w02);
            uint32_t a3 = packh2(w13, w12_);

            // B pre-paired: word index (8nt+g)*68 + s*8 + tk (+4 for k+8)
            const unsigned* bp = WhT + g * 68 + s * 8 + tk;
            #pragma unroll
            for (int nt = 0; nt < 8; nt++) {
                uint32_t ub0 = bp[nt * 544];
                uint32_t ub1 = bp[nt * 544 + 4];
                asm volatile(
                    "mma.sync.aligned.m16n8k16.row.col.f32.f16.f16.f32 "
                    "{%0,%1,%2,%3}, {%4,%5,%6,%7}, {%8,%9}, {%0,%1,%2,%3};"
                    : "+f"(c[nt][0]), "+f"(c[nt][1]), "+f"(c[nt][2]), "+f"(c[nt][3])
                    : "r"(a0), "r"(a1), "r"(a2), "r"(a3), "r"(ub0), "r"(ub1));
            }
        }
    }

    z0 += __shfl_xor_sync(0xffffffffu, z0, 1);
    z0 += __shfl_xor_sync(0xffffffffu, z0, 2);
    z1 += __shfl_xor_sync(0xffffffffu, z1, 1);
    z1 += __shfl_xor_sync(0xffffffffu, z1, 2);

    __syncthreads();
    // reduction region: 8 warpM x 8 nt x 32 lanes x float4 = 32768 B,
    // z at +32768 (1024 B). Total 33792 B = WhT size exactly.
    float4* red4 = (float4*)WhT;
    float2* zred = (float2*)((char*)WhT + 32768);

    if (kwarp == 1) {
        #pragma unroll
        for (int nt = 0; nt < 8; nt++)
            red4[(warpM * 8 + nt) * 32 + lane] =
                make_float4(c[nt][0], c[nt][1], c[nt][2], c[nt][3]);
        zred[warpM * 32 + lane] = make_float2(z0, z1);
    }
    __syncthreads();

    if (kwarp == 0) {
        float2 zz = zred[warpM * 32 + lane];
        float inv0 = 1.f / (z0 + zz.x);
        float inv1 = 1.f / (z1 + zz.y);

        float* o0 = out + (size_t)(b2048 + i0 + r0) * C_OUTT + tk * 2;
        float* o1 = out + (size_t)(b2048 + i0 + r1) * C_OUTT + tk * 2;
        #pragma unroll
        for (int nt = 0; nt < 8; nt++) {
            float4 v = red4[(warpM * 8 + nt) * 32 + lane];
            *(float2*)(o0 + nt * 8) =
                make_float2((c[nt][0] + v.x) * inv0, (c[nt][1] + v.y) * inv0);
            *(float2*)(o1 + nt * 8) =
                make_float2((c[nt][2] + v.z) * inv1, (c[nt][3] + v.w) * inv1);
        }
    }
}

// ---------------------------------------------------------------------------
extern "C" void kernel_launch(void* const* d_in, const int* in_sizes, int n_in,
                              void* d_out, int out_size)
{
    const float* x    = (const float*)d_in[0];   // (8,2048,128) f32
    const int*   A    = (const int*)d_in[1];     // (2048,2048) i32
    const float* W    = (const float*)d_in[2];   // (128,64) f32
    const float* attn = (const float*)d_in[3];   // (128,1) f32
    float* out = (float*)d_out;                  // (8,2048,64) f32

    const int prep_smem = (64 * 132 + 128 * 72 + 256) * 4;   // 71680 B
    cudaFuncSetAttribute(k_prep, cudaFuncAttributeMaxDynamicSharedMemorySize, prep_smem);

    k_prep<<<768, 256, prep_smem>>>(x, A, W, attn);
    k_gat <<<BB * (NN / 128), 512>>>(out);
}